// round 16
// baseline (speedup 1.0000x reference)
#include <cuda_runtime.h>
#include <cuda_bf16.h>
#include <float.h>
#include <math.h>

#define HH 8
#define CC 128
#define MAXN 65536
#define GB_NODES 64
#define GB_THREADS 128
#define LOG2E 1.4426950408889634f

// Scratch (allocation-free), aligned so per-node 32B rows support v8 loads.
__device__ __align__(256) float        g_p[MAXN * HH];
__device__ __align__(256) float        g_q[MAXN * HH];
__device__ __align__(256) unsigned int g_m[MAXN * 4];
__device__ __align__(256) float        g_s[MAXN * HH];     // sum -> z
__device__ __align__(256) float        g_selfa[MAXN * HH]; // self-loop alpha2

// ---------------------------------------------------------------------------
// L2 eviction policy (keep staged alpha resident across passes)
// ---------------------------------------------------------------------------
__device__ __forceinline__ unsigned long long polEvictLast() {
    unsigned long long p;
    asm("createpolicy.fractional.L2::evict_last.b64 %0, 1.0;" : "=l"(p));
    return p;
}

// ---------------------------------------------------------------------------
// 256-bit loads/stores
// ---------------------------------------------------------------------------
__device__ __forceinline__ void ldg256nc(const float* __restrict__ addr, float* v) {
    asm volatile("ld.global.nc.v8.f32 {%0,%1,%2,%3,%4,%5,%6,%7}, [%8];"
                 : "=f"(v[0]), "=f"(v[1]), "=f"(v[2]), "=f"(v[3]),
                   "=f"(v[4]), "=f"(v[5]), "=f"(v[6]), "=f"(v[7])
                 : "l"(addr));
}
__device__ __forceinline__ void ldg256(const float* addr, float* v) {
    asm volatile("ld.global.v8.f32 {%0,%1,%2,%3,%4,%5,%6,%7}, [%8];"
                 : "=f"(v[0]), "=f"(v[1]), "=f"(v[2]), "=f"(v[3]),
                   "=f"(v[4]), "=f"(v[5]), "=f"(v[6]), "=f"(v[7])
                 : "l"(addr));
}
__device__ __forceinline__ void stg256(float* addr, const float* v) {
    asm volatile("st.global.v8.f32 [%0], {%1,%2,%3,%4,%5,%6,%7,%8};"
                 :: "l"(addr), "f"(v[0]), "f"(v[1]), "f"(v[2]), "f"(v[3]),
                    "f"(v[4]), "f"(v[5]), "f"(v[6]), "f"(v[7]) : "memory");
}
__device__ __forceinline__ void stg256hint(float* addr, const float* v,
                                           unsigned long long pol) {
    asm volatile("st.global.L2::cache_hint.v8.f32 [%0], {%1,%2,%3,%4,%5,%6,%7,%8}, %9;"
                 :: "l"(addr), "f"(v[0]), "f"(v[1]), "f"(v[2]), "f"(v[3]),
                    "f"(v[4]), "f"(v[5]), "f"(v[6]), "f"(v[7]), "l"(pol) : "memory");
}
__device__ __forceinline__ void ldg256hint(const float* addr, float* v,
                                           unsigned long long pol) {
    asm volatile("ld.global.L2::cache_hint.v8.f32 {%0,%1,%2,%3,%4,%5,%6,%7}, [%8], %9;"
                 : "=f"(v[0]), "=f"(v[1]), "=f"(v[2]), "=f"(v[3]),
                   "=f"(v[4]), "=f"(v[5]), "=f"(v[6]), "=f"(v[7])
                 : "l"(addr), "l"(pol));
}

// ---------------------------------------------------------------------------
// vectorized reductions
// ---------------------------------------------------------------------------
__device__ __forceinline__ void redMaxBf16v8(unsigned int* addr, const unsigned int* u) {
    asm volatile("red.global.max.noftz.v8.bf16 [%0], {%1,%2,%3,%4,%5,%6,%7,%8};"
                 :: "l"(addr),
                    "h"((unsigned short)(u[0] & 0xFFFF)), "h"((unsigned short)(u[0] >> 16)),
                    "h"((unsigned short)(u[1] & 0xFFFF)), "h"((unsigned short)(u[1] >> 16)),
                    "h"((unsigned short)(u[2] & 0xFFFF)), "h"((unsigned short)(u[2] >> 16)),
                    "h"((unsigned short)(u[3] & 0xFFFF)), "h"((unsigned short)(u[3] >> 16))
                 : "memory");
}
__device__ __forceinline__ void redAddV4(float* addr, float a, float b, float c, float d) {
    asm volatile("red.global.add.v4.f32 [%0], {%1, %2, %3, %4};"
                 :: "l"(addr), "f"(a), "f"(b), "f"(c), "f"(d) : "memory");
}

// bf16 (packed in u32) -> float
__device__ __forceinline__ float bfLo(unsigned int u) { return __uint_as_float(u << 16); }
__device__ __forceinline__ float bfHi(unsigned int u) { return __uint_as_float(u & 0xFFFF0000u); }

// ---------------------------------------------------------------------------
// K1: block-tile GEMM + self-loop alpha + m/s init. 64 nodes/block.
// ---------------------------------------------------------------------------
__global__ __launch_bounds__(GB_THREADS)
void k_gemm(const float* __restrict__ x, const float* __restrict__ W,
            const float* __restrict__ b,
            float* __restrict__ p, float* __restrict__ q,
            float* __restrict__ selfa, unsigned int* __restrict__ m,
            float* __restrict__ s, int N) {
    __shared__ float  ws[16][CC];
    __shared__ float4 xs4[CC][17];
    __shared__ float  ps[GB_NODES][17];
    float* xsf = (float*)xs4;

    int tid   = threadIdx.x;
    int nbase = blockIdx.x * GB_NODES;

    for (int i = tid; i < 256 * HH; i += GB_THREADS) {
        int c = i >> 3, h = i & 7;
        if (c < CC) ws[h][c] = W[i];
        else        ws[HH + h][c - CC] = W[i];
    }

    {
        int c4l = tid >> 2;
        int ro  = tid & 3;
        for (int rb = 0; rb < GB_NODES; rb += 4) {
            int row = rb + ro;
            int n = nbase + row;
            if (n < N) {
                float4 v = *(const float4*)(x + (size_t)n * CC + c4l * 4);
                int cb = c4l * 4;
                xsf[(cb + 0) * 68 + row] = v.x;
                xsf[(cb + 1) * 68 + row] = v.y;
                xsf[(cb + 2) * 68 + row] = v.z;
                xsf[(cb + 3) * 68 + row] = v.w;
            }
        }
    }
    __syncthreads();

    int ng = tid & 15;
    int kq = tid >> 4;
    int k0 = kq * 2;

    float a00 = 0, a01 = 0, a10 = 0, a11 = 0;
    float a20 = 0, a21 = 0, a30 = 0, a31 = 0;
#pragma unroll 4
    for (int c = 0; c < CC; c++) {
        float  w0 = ws[k0][c], w1 = ws[k0 + 1][c];
        float4 xv = xs4[c][ng];
        a00 += xv.x * w0; a01 += xv.x * w1;
        a10 += xv.y * w0; a11 += xv.y * w1;
        a20 += xv.z * w0; a21 += xv.z * w1;
        a30 += xv.w * w0; a31 += xv.w * w1;
    }
    float av0[4] = { a00, a10, a20, a30 };
    float av1[4] = { a01, a11, a21, a31 };
    float* dst = (k0 < HH) ? p : q;
    int h0 = (k0 < HH) ? k0 : k0 - HH;
#pragma unroll
    for (int i = 0; i < 4; i++) {
        int n = nbase + ng * 4 + i;
        int rloc = ng * 4 + i;
        ps[rloc][k0]     = av0[i];
        ps[rloc][k0 + 1] = av1[i];
        if (n < N) {
            dst[n * HH + h0]     = av0[i];
            dst[n * HH + h0 + 1] = av1[i];
        }
    }
    __syncthreads();

    // self-loop alpha + m/s init: one thread per node (threads 0..63)
    if (tid < GB_NODES) {
        int n = nbase + tid;
        if (n < N) {
            float sa[HH];
            unsigned int hu[4];
#pragma unroll
            for (int h = 0; h < HH; h++) {
                float t = ps[tid][h] + ps[tid][HH + h] + b[h];   // w = 1
                t = (t > 0.0f) ? t : 0.2f * t;
                sa[h] = t * (100.0f * LOG2E);
            }
#pragma unroll
            for (int k = 0; k < 4; k++) {
                __nv_bfloat162 b2 = __floats2bfloat162_rn(sa[2 * k], sa[2 * k + 1]);
                hu[k] = *(unsigned int*)&b2;
            }
            stg256(selfa + n * HH, sa);
            *(uint4*)(m + n * 4) = make_uint4(hu[0], hu[1], hu[2], hu[3]);
            *(float4*)(s + n * HH)     = make_float4(0.f, 0.f, 0.f, 0.f);
            *(float4*)(s + n * HH + 4) = make_float4(0.f, 0.f, 0.f, 0.f);
        }
    }
}

// ---------------------------------------------------------------------------
// K2 (pass A): real edges only. a2 -> out (staged, L2 evict_last),
//              v8.bf16 red.max.
// ---------------------------------------------------------------------------
__global__ void k_passA(const int* __restrict__ row, const int* __restrict__ col,
                        const float* __restrict__ ea,
                        const float* __restrict__ p, const float* __restrict__ q,
                        const float* __restrict__ b,
                        unsigned int* __restrict__ m, float* __restrict__ out,
                        int E) {
    int e = blockIdx.x * blockDim.x + threadIdx.x;
    if (e >= E) return;
    int r = row[e], c = col[e];
    float w = fabsf(__ldcs(ea + e));

    float pv[HH], qv[HH];
    ldg256nc(p + r * HH, pv);
    ldg256nc(q + c * HH, qv);

    float av[HH];
#pragma unroll
    for (int h = 0; h < HH; h++) {
        float t = (pv[h] + qv[h] + b[h]) * w;
        t = (t > 0.0f) ? t : 0.2f * t;
        av[h] = t * (100.0f * LOG2E);
    }
    unsigned int hu[4];
#pragma unroll
    for (int k = 0; k < 4; k++) {
        __nv_bfloat162 b2 = __floats2bfloat162_rn(av[2 * k], av[2 * k + 1]);
        hu[k] = *(unsigned int*)&b2;
    }
    redMaxBf16v8(&m[r * 4], hu);

    stg256hint(out + (size_t)e * HH, av, polEvictLast());
}

// ---------------------------------------------------------------------------
// K3 (pass B): s[r] += exp2(a2 - m[r]); a2 read with evict_last hint so it
//              survives for pass C. Also writes row/col output (rebalanced).
// ---------------------------------------------------------------------------
__global__ void k_passB(const int* __restrict__ row, const int* __restrict__ col,
                        const unsigned int* __restrict__ m, float* __restrict__ s,
                        float* __restrict__ out, int E, int M, int writeIdx) {
    int e = blockIdx.x * blockDim.x + threadIdx.x;
    if (e >= E) return;
    int r = row[e];

    float av[HH];
    ldg256hint(out + (size_t)e * HH, av, polEvictLast());
    uint4 mu = __ldg((const uint4*)(m + r * 4));

    float ev[HH] = {
        exp2f(av[0] - bfLo(mu.x)), exp2f(av[1] - bfHi(mu.x)),
        exp2f(av[2] - bfLo(mu.y)), exp2f(av[3] - bfHi(mu.y)),
        exp2f(av[4] - bfLo(mu.z)), exp2f(av[5] - bfHi(mu.z)),
        exp2f(av[6] - bfLo(mu.w)), exp2f(av[7] - bfHi(mu.w)) };

    redAddV4(&s[r * HH],     ev[0], ev[1], ev[2], ev[3]);
    redAddV4(&s[r * HH + 4], ev[4], ev[5], ev[6], ev[7]);

    if (writeIdx) {
        __stcs(out + (size_t)M * HH + e,     (float)r);
        __stcs(out + (size_t)M * HH + M + e, (float)col[e]);
    }
}

// ---------------------------------------------------------------------------
// K3.5: z = m + log2(s + exp2(selfa - m)); emit self-loop rows + indices.
// ---------------------------------------------------------------------------
__global__ void k_z(const unsigned int* __restrict__ m,
                    const float* __restrict__ selfa,
                    float* __restrict__ s, float* __restrict__ out,
                    int N, int E, int M, int writeIdx) {
    int i = blockIdx.x * blockDim.x + threadIdx.x;
    if (i >= 2 * N) return;
    int n = i >> 1, half = i & 1;

    uint2  mu = *(const uint2*)(m + n * 4 + half * 2);
    float4 sv = *(const float4*)(s + n * HH + half * 4);
    float4 sa = *(const float4*)(selfa + n * HH + half * 4);
    float mv[4] = { bfLo(mu.x), bfHi(mu.x), bfLo(mu.y), bfHi(mu.y) };
    float svv[4] = { sv.x, sv.y, sv.z, sv.w };
    float sav[4] = { sa.x, sa.y, sa.z, sa.w };

    float zv[4], ov[4];
#pragma unroll
    for (int h = 0; h < 4; h++) {
        float tot = svv[h] + exp2f(sav[h] - mv[h]);
        zv[h] = mv[h] + __log2f(tot + 1e-16f);
        ov[h] = exp2f(sav[h] - zv[h]);
    }
    *(float4*)(s + n * HH + half * 4) = make_float4(zv[0], zv[1], zv[2], zv[3]);
    __stcs((float4*)(out + (size_t)(E + n) * HH + half * 4),
           make_float4(ov[0], ov[1], ov[2], ov[3]));

    if (writeIdx && half == 0) {
        __stcs(out + (size_t)M * HH + E + n,     (float)n);
        __stcs(out + (size_t)M * HH + M + E + n, (float)n);
    }
}

// ---------------------------------------------------------------------------
// K4 (pass C): out = exp2(a2 - z[r]) (a2 now L2-resident); final stores.
// ---------------------------------------------------------------------------
__global__ void k_passC(const int* __restrict__ row,
                        const float* __restrict__ s,
                        float* __restrict__ out, int E) {
    int e = blockIdx.x * blockDim.x + threadIdx.x;
    if (e >= E) return;
    int r = row[e];

    float av[HH];
    ldg256(out + (size_t)e * HH, av);
    float zv[HH];
    ldg256nc(s + r * HH, zv);

    float4 o0 = make_float4(exp2f(av[0] - zv[0]), exp2f(av[1] - zv[1]),
                            exp2f(av[2] - zv[2]), exp2f(av[3] - zv[3]));
    float4 o1 = make_float4(exp2f(av[4] - zv[4]), exp2f(av[5] - zv[5]),
                            exp2f(av[6] - zv[6]), exp2f(av[7] - zv[7]));
    __stcs((float4*)(out + (size_t)e * HH),     o0);
    __stcs((float4*)(out + (size_t)e * HH + 4), o1);
}

// ---------------------------------------------------------------------------
extern "C" void kernel_launch(void* const* d_in, const int* in_sizes, int n_in,
                              void* d_out, int out_size) {
    const float* x  = (const float*)d_in[0];   // [N, 128]
    const int*   ei = (const int*)d_in[1];     // [2, E]
    const float* ea = (const float*)d_in[2];   // [E]
    const float* W  = (const float*)d_in[3];   // [256, 8]
    const float* b  = (const float*)d_in[4];   // [8]
    float* out = (float*)d_out;

    int N = in_sizes[0] / CC;
    int E = in_sizes[2];
    int M = E + N;
    const int* row = ei;
    const int* col = ei + E;

    float *p, *q, *s, *selfa; unsigned int* m;
    cudaGetSymbolAddress((void**)&p, g_p);
    cudaGetSymbolAddress((void**)&q, g_q);
    cudaGetSymbolAddress((void**)&m, g_m);
    cudaGetSymbolAddress((void**)&s, g_s);
    cudaGetSymbolAddress((void**)&selfa, g_selfa);

    int writeIdx = (out_size >= M * (HH + 2)) ? 1 : 0;

    int gblocks = (N + GB_NODES - 1) / GB_NODES;
    k_gemm<<<gblocks, GB_THREADS>>>(x, W, b, p, q, selfa, m, s, N);

    int eblocks = (E + 255) / 256;
    k_passA<<<eblocks, 256>>>(row, col, ea, p, q, b, m, out, E);
    k_passB<<<eblocks, 256>>>(row, col, m, s, out, E, M, writeIdx);
    k_z<<<(2 * N + 255) / 256, 256>>>(m, selfa, s, out, N, E, M, writeIdx);
    k_passC<<<eblocks, 256>>>(row, s, out, E);
}

// round 17
// speedup vs baseline: 1.0179x; 1.0179x over previous
#include <cuda_runtime.h>
#include <cuda_bf16.h>
#include <float.h>
#include <math.h>

#define HH 8
#define CC 128
#define MAXN 65536
#define GB_NODES 64
#define GB_THREADS 128
#define LOG2E 1.4426950408889634f

// Scratch (allocation-free), aligned so per-node 32B rows support v8 loads.
__device__ __align__(256) float        g_p[MAXN * HH];
__device__ __align__(256) float        g_q[MAXN * HH];
__device__ __align__(256) unsigned int g_m[MAXN * 4];
__device__ __align__(256) float        g_s[MAXN * HH];     // sum -> z
__device__ __align__(256) float        g_selfa[MAXN * HH]; // self-loop alpha2

// ---------------------------------------------------------------------------
// 256-bit loads/stores
// ---------------------------------------------------------------------------
__device__ __forceinline__ void ldg256nc(const float* __restrict__ addr, float* v) {
    asm volatile("ld.global.nc.v8.f32 {%0,%1,%2,%3,%4,%5,%6,%7}, [%8];"
                 : "=f"(v[0]), "=f"(v[1]), "=f"(v[2]), "=f"(v[3]),
                   "=f"(v[4]), "=f"(v[5]), "=f"(v[6]), "=f"(v[7])
                 : "l"(addr));
}
__device__ __forceinline__ void ldg256(const float* addr, float* v) {
    asm volatile("ld.global.v8.f32 {%0,%1,%2,%3,%4,%5,%6,%7}, [%8];"
                 : "=f"(v[0]), "=f"(v[1]), "=f"(v[2]), "=f"(v[3]),
                   "=f"(v[4]), "=f"(v[5]), "=f"(v[6]), "=f"(v[7])
                 : "l"(addr));
}
__device__ __forceinline__ void stg256(float* addr, const float* v) {
    asm volatile("st.global.v8.f32 [%0], {%1,%2,%3,%4,%5,%6,%7,%8};"
                 :: "l"(addr), "f"(v[0]), "f"(v[1]), "f"(v[2]), "f"(v[3]),
                    "f"(v[4]), "f"(v[5]), "f"(v[6]), "f"(v[7]) : "memory");
}

// ---------------------------------------------------------------------------
// vectorized reductions
// ---------------------------------------------------------------------------
__device__ __forceinline__ void redMaxBf16v8(unsigned int* addr, const unsigned int* u) {
    asm volatile("red.global.max.noftz.v8.bf16 [%0], {%1,%2,%3,%4,%5,%6,%7,%8};"
                 :: "l"(addr),
                    "h"((unsigned short)(u[0] & 0xFFFF)), "h"((unsigned short)(u[0] >> 16)),
                    "h"((unsigned short)(u[1] & 0xFFFF)), "h"((unsigned short)(u[1] >> 16)),
                    "h"((unsigned short)(u[2] & 0xFFFF)), "h"((unsigned short)(u[2] >> 16)),
                    "h"((unsigned short)(u[3] & 0xFFFF)), "h"((unsigned short)(u[3] >> 16))
                 : "memory");
}
__device__ __forceinline__ void redAddV4(float* addr, float a, float b, float c, float d) {
    asm volatile("red.global.add.v4.f32 [%0], {%1, %2, %3, %4};"
                 :: "l"(addr), "f"(a), "f"(b), "f"(c), "f"(d) : "memory");
}

// bf16 (packed in u32) -> float
__device__ __forceinline__ float bfLo(unsigned int u) { return __uint_as_float(u << 16); }
__device__ __forceinline__ float bfHi(unsigned int u) { return __uint_as_float(u & 0xFFFF0000u); }

// ---------------------------------------------------------------------------
// K1: block-tile GEMM + self-loop alpha + m/s init. 64 nodes/block.
// ---------------------------------------------------------------------------
__global__ __launch_bounds__(GB_THREADS)
void k_gemm(const float* __restrict__ x, const float* __restrict__ W,
            const float* __restrict__ b,
            float* __restrict__ p, float* __restrict__ q,
            float* __restrict__ selfa, unsigned int* __restrict__ m,
            float* __restrict__ s, int N) {
    __shared__ float  ws[16][CC];
    __shared__ float4 xs4[CC][17];
    __shared__ float  ps[GB_NODES][17];
    float* xsf = (float*)xs4;

    int tid   = threadIdx.x;
    int nbase = blockIdx.x * GB_NODES;

    for (int i = tid; i < 256 * HH; i += GB_THREADS) {
        int c = i >> 3, h = i & 7;
        if (c < CC) ws[h][c] = W[i];
        else        ws[HH + h][c - CC] = W[i];
    }

    {
        int c4l = tid >> 2;
        int ro  = tid & 3;
        for (int rb = 0; rb < GB_NODES; rb += 4) {
            int row = rb + ro;
            int n = nbase + row;
            if (n < N) {
                float4 v = *(const float4*)(x + (size_t)n * CC + c4l * 4);
                int cb = c4l * 4;
                xsf[(cb + 0) * 68 + row] = v.x;
                xsf[(cb + 1) * 68 + row] = v.y;
                xsf[(cb + 2) * 68 + row] = v.z;
                xsf[(cb + 3) * 68 + row] = v.w;
            }
        }
    }
    __syncthreads();

    int ng = tid & 15;
    int kq = tid >> 4;
    int k0 = kq * 2;

    float a00 = 0, a01 = 0, a10 = 0, a11 = 0;
    float a20 = 0, a21 = 0, a30 = 0, a31 = 0;
#pragma unroll 4
    for (int c = 0; c < CC; c++) {
        float  w0 = ws[k0][c], w1 = ws[k0 + 1][c];
        float4 xv = xs4[c][ng];
        a00 += xv.x * w0; a01 += xv.x * w1;
        a10 += xv.y * w0; a11 += xv.y * w1;
        a20 += xv.z * w0; a21 += xv.z * w1;
        a30 += xv.w * w0; a31 += xv.w * w1;
    }
    float av0[4] = { a00, a10, a20, a30 };
    float av1[4] = { a01, a11, a21, a31 };
    float* dst = (k0 < HH) ? p : q;
    int h0 = (k0 < HH) ? k0 : k0 - HH;
#pragma unroll
    for (int i = 0; i < 4; i++) {
        int n = nbase + ng * 4 + i;
        int rloc = ng * 4 + i;
        ps[rloc][k0]     = av0[i];
        ps[rloc][k0 + 1] = av1[i];
        if (n < N) {
            dst[n * HH + h0]     = av0[i];
            dst[n * HH + h0 + 1] = av1[i];
        }
    }
    __syncthreads();

    // self-loop alpha + m/s init: one thread per node (threads 0..63)
    if (tid < GB_NODES) {
        int n = nbase + tid;
        if (n < N) {
            float sa[HH];
            unsigned int hu[4];
#pragma unroll
            for (int h = 0; h < HH; h++) {
                float t = ps[tid][h] + ps[tid][HH + h] + b[h];   // w = 1
                t = (t > 0.0f) ? t : 0.2f * t;
                sa[h] = t * (100.0f * LOG2E);
            }
#pragma unroll
            for (int k = 0; k < 4; k++) {
                __nv_bfloat162 b2 = __floats2bfloat162_rn(sa[2 * k], sa[2 * k + 1]);
                hu[k] = *(unsigned int*)&b2;
            }
            stg256(selfa + n * HH, sa);
            *(uint4*)(m + n * 4) = make_uint4(hu[0], hu[1], hu[2], hu[3]);
            *(float4*)(s + n * HH)     = make_float4(0.f, 0.f, 0.f, 0.f);
            *(float4*)(s + n * HH + 4) = make_float4(0.f, 0.f, 0.f, 0.f);
        }
    }
}

// ---------------------------------------------------------------------------
// K2 (pass A): real edges only. a2 -> out (staged), v8.bf16 red.max.
// ---------------------------------------------------------------------------
__global__ void k_passA(const int* __restrict__ row, const int* __restrict__ col,
                        const float* __restrict__ ea,
                        const float* __restrict__ p, const float* __restrict__ q,
                        const float* __restrict__ b,
                        unsigned int* __restrict__ m, float* __restrict__ out,
                        int E) {
    int e = blockIdx.x * blockDim.x + threadIdx.x;
    if (e >= E) return;
    int r = row[e], c = col[e];
    float w = fabsf(__ldcs(ea + e));

    float pv[HH], qv[HH];
    ldg256nc(p + r * HH, pv);
    ldg256nc(q + c * HH, qv);

    float av[HH];
#pragma unroll
    for (int h = 0; h < HH; h++) {
        float t = (pv[h] + qv[h] + b[h]) * w;
        t = (t > 0.0f) ? t : 0.2f * t;
        av[h] = t * (100.0f * LOG2E);
    }
    unsigned int hu[4];
#pragma unroll
    for (int k = 0; k < 4; k++) {
        __nv_bfloat162 b2 = __floats2bfloat162_rn(av[2 * k], av[2 * k + 1]);
        hu[k] = *(unsigned int*)&b2;
    }
    redMaxBf16v8(&m[r * 4], hu);

    stg256(out + (size_t)e * HH, av);
}

// ---------------------------------------------------------------------------
// K3 (pass B): s[r] += exp2(a2 - m[r]); also writes row/col output
//              (rebalanced from pass C). No alpha writeback.
// ---------------------------------------------------------------------------
__global__ void k_passB(const int* __restrict__ row, const int* __restrict__ col,
                        const unsigned int* __restrict__ m, float* __restrict__ s,
                        float* __restrict__ out, int E, int M, int writeIdx) {
    int e = blockIdx.x * blockDim.x + threadIdx.x;
    if (e >= E) return;
    int r = row[e];

    float av[HH];
    ldg256nc(out + (size_t)e * HH, av);
    uint4 mu = __ldg((const uint4*)(m + r * 4));

    float ev[HH] = {
        exp2f(av[0] - bfLo(mu.x)), exp2f(av[1] - bfHi(mu.x)),
        exp2f(av[2] - bfLo(mu.y)), exp2f(av[3] - bfHi(mu.y)),
        exp2f(av[4] - bfLo(mu.z)), exp2f(av[5] - bfHi(mu.z)),
        exp2f(av[6] - bfLo(mu.w)), exp2f(av[7] - bfHi(mu.w)) };

    redAddV4(&s[r * HH],     ev[0], ev[1], ev[2], ev[3]);
    redAddV4(&s[r * HH + 4], ev[4], ev[5], ev[6], ev[7]);

    if (writeIdx) {
        __stcs(out + (size_t)M * HH + e,     (float)r);
        __stcs(out + (size_t)M * HH + M + e, (float)col[e]);
    }
}

// ---------------------------------------------------------------------------
// K3.5: z = m + log2(s + exp2(selfa - m)); emit self-loop rows + indices.
// ---------------------------------------------------------------------------
__global__ void k_z(const unsigned int* __restrict__ m,
                    const float* __restrict__ selfa,
                    float* __restrict__ s, float* __restrict__ out,
                    int N, int E, int M, int writeIdx) {
    int i = blockIdx.x * blockDim.x + threadIdx.x;
    if (i >= 2 * N) return;
    int n = i >> 1, half = i & 1;

    uint2  mu = *(const uint2*)(m + n * 4 + half * 2);
    float4 sv = *(const float4*)(s + n * HH + half * 4);
    float4 sa = *(const float4*)(selfa + n * HH + half * 4);
    float mv[4] = { bfLo(mu.x), bfHi(mu.x), bfLo(mu.y), bfHi(mu.y) };
    float svv[4] = { sv.x, sv.y, sv.z, sv.w };
    float sav[4] = { sa.x, sa.y, sa.z, sa.w };

    float zv[4], ov[4];
#pragma unroll
    for (int h = 0; h < 4; h++) {
        float tot = svv[h] + exp2f(sav[h] - mv[h]);
        zv[h] = mv[h] + __log2f(tot + 1e-16f);
        ov[h] = exp2f(sav[h] - zv[h]);
    }
    *(float4*)(s + n * HH + half * 4) = make_float4(zv[0], zv[1], zv[2], zv[3]);
    __stcs((float4*)(out + (size_t)(E + n) * HH + half * 4),
           make_float4(ov[0], ov[1], ov[2], ov[3]));

    if (writeIdx && half == 0) {
        __stcs(out + (size_t)M * HH + E + n,     (float)n);
        __stcs(out + (size_t)M * HH + M + E + n, (float)n);
    }
}

// ---------------------------------------------------------------------------
// K4 (pass C): out = exp2(a2 - z[r]); lightest pass (no index writes).
// ---------------------------------------------------------------------------
__global__ void k_passC(const int* __restrict__ row,
                        const float* __restrict__ s,
                        float* __restrict__ out, int E) {
    int e = blockIdx.x * blockDim.x + threadIdx.x;
    if (e >= E) return;
    int r = row[e];

    float av[HH];
    ldg256(out + (size_t)e * HH, av);
    float zv[HH];
    ldg256nc(s + r * HH, zv);

    float4 o0 = make_float4(exp2f(av[0] - zv[0]), exp2f(av[1] - zv[1]),
                            exp2f(av[2] - zv[2]), exp2f(av[3] - zv[3]));
    float4 o1 = make_float4(exp2f(av[4] - zv[4]), exp2f(av[5] - zv[5]),
                            exp2f(av[6] - zv[6]), exp2f(av[7] - zv[7]));
    __stcs((float4*)(out + (size_t)e * HH),     o0);
    __stcs((float4*)(out + (size_t)e * HH + 4), o1);
}

// ---------------------------------------------------------------------------
extern "C" void kernel_launch(void* const* d_in, const int* in_sizes, int n_in,
                              void* d_out, int out_size) {
    const float* x  = (const float*)d_in[0];   // [N, 128]
    const int*   ei = (const int*)d_in[1];     // [2, E]
    const float* ea = (const float*)d_in[2];   // [E]
    const float* W  = (const float*)d_in[3];   // [256, 8]
    const float* b  = (const float*)d_in[4];   // [8]
    float* out = (float*)d_out;

    int N = in_sizes[0] / CC;
    int E = in_sizes[2];
    int M = E + N;
    const int* row = ei;
    const int* col = ei + E;

    float *p, *q, *s, *selfa; unsigned int* m;
    cudaGetSymbolAddress((void**)&p, g_p);
    cudaGetSymbolAddress((void**)&q, g_q);
    cudaGetSymbolAddress((void**)&m, g_m);
    cudaGetSymbolAddress((void**)&s, g_s);
    cudaGetSymbolAddress((void**)&selfa, g_selfa);

    int writeIdx = (out_size >= M * (HH + 2)) ? 1 : 0;

    int gblocks = (N + GB_NODES - 1) / GB_NODES;
    k_gemm<<<gblocks, GB_THREADS>>>(x, W, b, p, q, selfa, m, s, N);

    int eblocks = (E + 255) / 256;
    k_passA<<<eblocks, 256>>>(row, col, ea, p, q, b, m, out, E);
    k_passB<<<eblocks, 256>>>(row, col, m, s, out, E, M, writeIdx);
    k_z<<<(2 * N + 255) / 256, 256>>>(m, selfa, s, out, N, E, M, writeIdx);
    k_passC<<<eblocks, 256>>>(row, s, out, E);
}